// round 5
// baseline (speedup 1.0000x reference)
#include <cuda_runtime.h>
#include <math.h>

// Fixed shapes: (B,H,W,C,T) = (64,80,80,80,50)
#define BB    64
#define HH    80
#define WW    80
#define HWC   (HH*WW)          // 6400
#define CC    80
#define DD    (5+CC)           // 85
#define TT    50
#define HT    25               // half-batch targets
#define NT    (BB*TT)          // 3200
#define NCELL (BB*HWC)         // 409600

#define NBLK  296              // one wave at 2 blocks/SM on 148 SMs
#define NTHR  1024
#define GSTRIDE (NBLK*NTHR)    // 303104
#define PER   2

#define NTB   128              // target blocks (half-batch each)

#define LAMBDA_COORD 5.0
#define LAMBDA_NOOBJ 0.5

// Per-block partials: every slot written on every replay -> no init kernel.
__device__ float g_conf_part[NBLK];
__device__ float g_coord_part[NTB];
__device__ float g_cls_part[NTB];
__device__ float g_obj_part[NTB];
__device__ float g_corr_part[NTB];
__device__ int   g_cnt_part[NTB];
__device__ unsigned int g_counter = 0;   // reset by last block each replay

__device__ __forceinline__ float softplus_pos(float x) {
    return log1pf(__expf(-fabsf(x))) + fmaxf(x, 0.0f);
}

__global__ void __launch_bounds__(NTHR, 2)
k_fused(const float* __restrict__ pred, const float* __restrict__ targets,
        float* __restrict__ out) {
    const int tid = threadIdx.x;
    const int blk = blockIdx.x;
    const int lane = tid & 31;
    const int warp = tid >> 5;

    // ---- issue the independent conf loads up front (MLP) ----
    const int base = blk * NTHR + tid;
    const int i1 = base + GSTRIDE;
    const float c0 = (base < NCELL) ? __ldg(&pred[(size_t)base * DD + 4]) : 0.0f;
    const float c1 = (i1   < NCELL) ? __ldg(&pred[(size_t)i1   * DD + 4]) : 0.0f;

    __shared__ int   s_cell[TT];
    __shared__ float s_tx[TT], s_ty[TT], s_tw[TT], s_th[TT];
    __shared__ int   s_cid[TT];
    __shared__ float s_c[32], s_l[32], s_o[32], s_r[32];
    __shared__ int   s_n[32];
    __shared__ double sd[8];
    __shared__ bool  isLast;

    // ---- target branch: blocks 0..127, half a batch each ----
    if (blk < NTB) {
        const int b    = blk >> 1;          // batch
        const int tofs = (blk & 1) * HT;    // 0 or 25
        // all 50 cells of the batch go to shared (needed for dedup)
        if (tid < TT) {
            const float* tg = targets + ((size_t)b * TT + tid) * 5;
            float cx = tg[1], cy = tg[2], w = tg[3], h = tg[4];
            int gx = (int)floorf(cx * WW);
            int gy = (int)floorf(cy * HH);
            s_cell[tid] = gy * WW + gx;
            s_tx[tid] = cx * WW - (float)gx;
            s_ty[tid] = cy * HH - (float)gy;
            s_tw[tid] = logf(w * WW + 1e-16f);
            s_th[tid] = logf(h * HH + 1e-16f);
            s_cid[tid] = (int)tg[0];
        }
        __syncthreads();

        float coordv = 0.f, clsv = 0.f, objv = 0.f, corrv = 0.f;
        int cntv = 0;
        // one round: warps 0..24 each take one target of this half
        if (warp < HT) {
            const int t = tofs + warp;
            const int cell = s_cell[t];
            const float* g = pred + ((size_t)b * HWC + cell) * DD;
            // warp-cooperative logsumexp over 80 classes
            float v0 = __ldg(&g[5 + lane]);
            float v1 = __ldg(&g[5 + 32 + lane]);
            float v2 = (lane < 16) ? __ldg(&g[5 + 64 + lane]) : -1e30f;
            float m = fmaxf(fmaxf(v0, v1), v2);
            #pragma unroll
            for (int o = 16; o > 0; o >>= 1)
                m = fmaxf(m, __shfl_xor_sync(0xffffffffu, m, o));
            float s = __expf(v0 - m) + __expf(v1 - m) +
                      ((lane < 16) ? __expf(v2 - m) : 0.0f);
            #pragma unroll
            for (int o = 16; o > 0; o >>= 1)
                s += __shfl_xor_sync(0xffffffffu, s, o);

            if (lane == 0) {
                clsv = -(__ldg(&g[5 + s_cid[t]]) - m - logf(s));
                float sx = 1.0f / (1.0f + __expf(-__ldg(&g[0])));
                float sy = 1.0f / (1.0f + __expf(-__ldg(&g[1])));
                float dx = sx - s_tx[t], dy = sy - s_ty[t];
                float dw = __ldg(&g[2]) - s_tw[t], dh = __ldg(&g[3]) - s_th[t];
                coordv = 0.5f * (dx * dx + dy * dy) + 0.5f * (dw * dw + dh * dh);
                // first occurrence across the WHOLE batch (j < t, global order)
                bool uniq = true;
                for (int j = 0; j < t; j++)
                    if (s_cell[j] == cell) { uniq = false; break; }
                if (uniq) {
                    cntv = 1;
                    float cl = __ldg(&g[4]);
                    float bse = log1pf(__expf(-fabsf(cl)));
                    objv  = bse + fmaxf(-cl, 0.0f);   // softplus(-cl)
                    corrv = bse + fmaxf( cl, 0.0f);   // softplus(cl)
                }
            }
        }
        if (lane == 0) {
            s_c[warp] = coordv; s_l[warp] = clsv;
            s_o[warp] = objv;   s_r[warp] = corrv;
            s_n[warp] = cntv;
        }
        __syncthreads();
        if (tid == 0) {
            float a = 0, bsum = 0, c = 0, d = 0; int n = 0;
            #pragma unroll
            for (int i = 0; i < HT; i++) {
                a += s_c[i]; bsum += s_l[i]; c += s_o[i]; d += s_r[i]; n += s_n[i];
            }
            g_coord_part[blk] = a; g_cls_part[blk] = bsum;
            g_obj_part[blk] = c;   g_corr_part[blk] = d;
            g_cnt_part[blk] = n;
        }
        __syncthreads();
    }

    // ---- conf partial: block-reduce softplus over this thread's cells ----
    {
        float s = 0.0f;
        if (base < NCELL) s += softplus_pos(c0);
        if (i1   < NCELL) s += softplus_pos(c1);
        #pragma unroll
        for (int o = 16; o > 0; o >>= 1)
            s += __shfl_xor_sync(0xffffffffu, s, o);
        if (lane == 0) s_c[warp] = s;
        __syncthreads();
        if (tid == 0) {
            float t = 0;
            #pragma unroll
            for (int i = 0; i < 32; i++) t += s_c[i];
            g_conf_part[blk] = t;
        }
    }

    // ---- last block finalizes ----
    __threadfence();
    if (tid == 0) {
        unsigned old = atomicAdd(&g_counter, 1);
        isLast = (old == (unsigned)(NBLK - 1));
    }
    __syncthreads();
    if (!isLast) return;
    __threadfence();

    // 6 parallel warp reductions
    double r = 0.0;
    if (warp == 0) {
        for (int i = lane; i < NBLK; i += 32) r += (double)g_conf_part[i];
    } else if (warp == 1) {
        for (int i = lane; i < NTB; i += 32) r += (double)g_coord_part[i];
    } else if (warp == 2) {
        for (int i = lane; i < NTB; i += 32) r += (double)g_cls_part[i];
    } else if (warp == 3) {
        for (int i = lane; i < NTB; i += 32) r += (double)g_obj_part[i];
    } else if (warp == 4) {
        for (int i = lane; i < NTB; i += 32) r += (double)g_corr_part[i];
    } else if (warp == 5) {
        for (int i = lane; i < NTB; i += 32) r += (double)g_cnt_part[i];
    }
    #pragma unroll
    for (int o = 16; o > 0; o >>= 1)
        r += __shfl_down_sync(0xffffffffu, r, o);
    if (lane == 0 && warp < 6) sd[warp] = r;
    __syncthreads();

    if (tid == 0) {
        double alls = sd[0], coord = sd[1], cls = sd[2];
        double objs = sd[3], corr = sd[4];
        int nobj = (int)(sd[5] + 0.5);
        double n_noobj = (double)(NCELL - nobj);
        double noobj_sum = alls - corr;
        double conf_obj = objs / (double)(nobj > 0 ? nobj : 1);
        double conf_noobj = noobj_sum / n_noobj;
        double num_obj = (double)NT;
        double total = LAMBDA_COORD * coord / num_obj
                     + conf_obj / num_obj
                     + LAMBDA_NOOBJ * conf_noobj / n_noobj
                     + cls / num_obj;
        out[0] = (float)total;
        g_counter = 0;   // reset for next graph replay
    }
}

extern "C" void kernel_launch(void* const* d_in, const int* in_sizes, int n_in,
                              void* d_out, int out_size) {
    const float* pred    = (const float*)d_in[0];
    const float* targets = (const float*)d_in[1];
    float* out = (float*)d_out;
    (void)in_sizes; (void)n_in; (void)out_size;

    k_fused<<<NBLK, NTHR>>>(pred, targets, out);
}

// round 6
// speedup vs baseline: 1.4251x; 1.4251x over previous
#include <cuda_runtime.h>
#include <math.h>

// Fixed shapes: (B,H,W,C,T) = (64,80,80,80,50)
#define BB    64
#define HH    80
#define WW    80
#define HWC   (HH*WW)          // 6400
#define CC    80
#define DD    (5+CC)           // 85
#define TT    50
#define NT    (BB*TT)          // 3200
#define NCELL (BB*HWC)         // 409600

#define NCBLK 1600             // conf blocks: 1600 x 256 = 409600 (R1-proven shape)
#define NTBLK 400              // blocks that also carry 8 targets each

#define LAMBDA_COORD 5.0
#define LAMBDA_NOOBJ 0.5

// Per-block partials: every slot written on every replay -> no init kernel.
__device__ float g_conf_part[NCBLK];
__device__ float g_coord_part[NTBLK];
__device__ float g_cls_part[NTBLK];
__device__ float g_obj_part[NTBLK];
__device__ float g_corr_part[NTBLK];
__device__ int   g_cnt_part[NTBLK];

__device__ __forceinline__ float softplus_pos(float x) {
    return log1pf(__expf(-fabsf(x))) + fmaxf(x, 0.0f);
}

__global__ void __launch_bounds__(256, 8)
k_main(const float* __restrict__ pred, const float* __restrict__ targets) {
    const int tid  = threadIdx.x;
    const int blk  = blockIdx.x;
    const int lane = tid & 31;
    const int warp = tid >> 5;

    // ---- conf load issued first (overlaps target branch) ----
    const int ci = blk * 256 + tid;                 // < NCELL exactly
    const float cv = __ldg(&pred[(size_t)ci * DD + 4]);

    __shared__ float s_c[8], s_l[8], s_o[8], s_r[8];
    __shared__ int   s_n[8];

    // ---- target branch: blocks 0..399, 8 targets each (warp-per-target) ----
    if (blk < NTBLK) {
        const int tg   = blk * 8 + warp;            // global target id < NT
        const int b    = tg / TT;
        const int tIdx = tg % TT;

        // all lanes load this target's 5 fields (uniform address -> broadcast)
        const float* tp = targets + (size_t)tg * 5;
        const int   cid = (int)tp[0];
        const float cx = tp[1], cy = tp[2], w = tp[3], h = tp[4];
        const int gx = (int)floorf(cx * WW);
        const int gy = (int)floorf(cy * HH);
        const int cell = gy * WW + gx;
        const float tx = cx * WW - (float)gx;
        const float ty = cy * HH - (float)gy;

        // dedup: any earlier target j<tIdx in this batch with the same cell?
        bool hit = false;
        #pragma unroll
        for (int r = 0; r < 2; r++) {
            int j = lane + r * 32;
            if (j < tIdx) {
                const float* pj = targets + ((size_t)b * TT + j) * 5;
                int pgx = (int)floorf(pj[1] * WW);
                int pgy = (int)floorf(pj[2] * HH);
                if (pgy * WW + pgx == cell) hit = true;
            }
        }
        const bool uniq = (__ballot_sync(0xffffffffu, hit) == 0u);

        // warp-cooperative logsumexp over 80 classes
        const float* g = pred + ((size_t)b * HWC + cell) * DD;
        float v0 = __ldg(&g[5 + lane]);
        float v1 = __ldg(&g[5 + 32 + lane]);
        float v2 = (lane < 16) ? __ldg(&g[5 + 64 + lane]) : -1e30f;
        float m = fmaxf(fmaxf(v0, v1), v2);
        #pragma unroll
        for (int o = 16; o > 0; o >>= 1)
            m = fmaxf(m, __shfl_xor_sync(0xffffffffu, m, o));
        float s = __expf(v0 - m) + __expf(v1 - m) +
                  ((lane < 16) ? __expf(v2 - m) : 0.0f);
        #pragma unroll
        for (int o = 16; o > 0; o >>= 1)
            s += __shfl_xor_sync(0xffffffffu, s, o);

        if (lane == 0) {
            float clsv = -(__ldg(&g[5 + cid]) - m - logf(s));
            float sx = 1.0f / (1.0f + __expf(-__ldg(&g[0])));
            float sy = 1.0f / (1.0f + __expf(-__ldg(&g[1])));
            float tw = logf(w * WW + 1e-16f);
            float th = logf(h * HH + 1e-16f);
            float dx = sx - tx, dy = sy - ty;
            float dw = __ldg(&g[2]) - tw, dh = __ldg(&g[3]) - th;
            float coordv = 0.5f * (dx * dx + dy * dy) + 0.5f * (dw * dw + dh * dh);
            float objv = 0.f, corrv = 0.f;
            if (uniq) {
                float cl = __ldg(&g[4]);
                float bse = log1pf(__expf(-fabsf(cl)));
                objv  = bse + fmaxf(-cl, 0.0f);   // softplus(-cl)
                corrv = bse + fmaxf( cl, 0.0f);   // softplus(cl)
            }
            s_c[warp] = coordv; s_l[warp] = clsv;
            s_o[warp] = objv;   s_r[warp] = corrv;
            s_n[warp] = uniq ? 1 : 0;
        }
        __syncthreads();
        if (tid == 0) {
            float a = 0, bsum = 0, c = 0, d = 0; int n = 0;
            #pragma unroll
            for (int i = 0; i < 8; i++) {
                a += s_c[i]; bsum += s_l[i]; c += s_o[i]; d += s_r[i]; n += s_n[i];
            }
            g_coord_part[blk] = a; g_cls_part[blk] = bsum;
            g_obj_part[blk] = c;   g_corr_part[blk] = d;
            g_cnt_part[blk] = n;
        }
        __syncthreads();   // protect s_c reuse below
    }

    // ---- conf partial: block-reduce softplus (8 warps) ----
    {
        float s = softplus_pos(cv);
        #pragma unroll
        for (int o = 16; o > 0; o >>= 1)
            s += __shfl_xor_sync(0xffffffffu, s, o);
        if (lane == 0) s_c[warp] = s;
        __syncthreads();
        if (tid == 0) {
            float t = 0;
            #pragma unroll
            for (int i = 0; i < 8; i++) t += s_c[i];
            g_conf_part[blk] = t;
        }
    }
}

// Block-wide double reduce, 1024 threads; result valid in thread 0.
__device__ __forceinline__ double blockReduceD(double v, double* sd) {
    int lane = threadIdx.x & 31, w = threadIdx.x >> 5;
    #pragma unroll
    for (int o = 16; o > 0; o >>= 1) v += __shfl_xor_sync(0xffffffffu, v, o);
    if (lane == 0) sd[w] = v;
    __syncthreads();
    v = (threadIdx.x < 32) ? sd[threadIdx.x] : 0.0;
    if (w == 0) {
        #pragma unroll
        for (int o = 16; o > 0; o >>= 1) v += __shfl_xor_sync(0xffffffffu, v, o);
    }
    __syncthreads();
    return v;
}

__global__ void __launch_bounds__(1024)
k_final(float* __restrict__ out) {
    const int tid = threadIdx.x;
    __shared__ double sd[32];

    double v = 0.0;
    for (int i = tid; i < NCBLK; i += 1024) v += (double)g_conf_part[i];
    double alls = blockReduceD(v, sd);

    double coord = blockReduceD(tid < NTBLK ? (double)g_coord_part[tid] : 0.0, sd);
    double cls   = blockReduceD(tid < NTBLK ? (double)g_cls_part[tid]   : 0.0, sd);
    double objs  = blockReduceD(tid < NTBLK ? (double)g_obj_part[tid]   : 0.0, sd);
    double corr  = blockReduceD(tid < NTBLK ? (double)g_corr_part[tid]  : 0.0, sd);
    double cnt   = blockReduceD(tid < NTBLK ? (double)g_cnt_part[tid]   : 0.0, sd);

    if (tid == 0) {
        int nobj = (int)(cnt + 0.5);
        double n_noobj = (double)(NCELL - nobj);
        double noobj_sum = alls - corr;
        double conf_obj = objs / (double)(nobj > 0 ? nobj : 1);
        double conf_noobj = noobj_sum / n_noobj;
        double num_obj = (double)NT;
        double total = LAMBDA_COORD * coord / num_obj
                     + conf_obj / num_obj
                     + LAMBDA_NOOBJ * conf_noobj / n_noobj
                     + cls / num_obj;
        out[0] = (float)total;
    }
}

extern "C" void kernel_launch(void* const* d_in, const int* in_sizes, int n_in,
                              void* d_out, int out_size) {
    const float* pred    = (const float*)d_in[0];
    const float* targets = (const float*)d_in[1];
    float* out = (float*)d_out;
    (void)in_sizes; (void)n_in; (void)out_size;

    k_main<<<NCBLK, 256>>>(pred, targets);
    k_final<<<1, 1024>>>(out);
}

// round 7
// speedup vs baseline: 1.6127x; 1.1316x over previous
#include <cuda_runtime.h>
#include <math.h>

// Fixed shapes: (B,H,W,C,T) = (64,80,80,80,50)
#define BB    64
#define HH    80
#define WW    80
#define HWC   (HH*WW)          // 6400
#define CC    80
#define DD    (5+CC)           // 85
#define TT    50
#define NT    (BB*TT)          // 3200
#define NCELL (BB*HWC)         // 409600

#define NCBLK 1600             // 1600 x 256 = 409600 (proven shape)
#define NTBLK 400              // blocks that also carry 8 targets each

#define LAMBDA_COORD 5.0
#define LAMBDA_NOOBJ 0.5

// Per-block partials: every slot written on every replay -> no init kernel.
__device__ float g_conf_part[NCBLK];
__device__ float g_coord_part[NTBLK];
__device__ float g_cls_part[NTBLK];
__device__ float g_obj_part[NTBLK];
__device__ float g_corr_part[NTBLK];
__device__ int   g_cnt_part[NTBLK];
__device__ unsigned int g_counter = 0;   // reset by finalizing block each replay

__device__ __forceinline__ float softplus_pos(float x) {
    return log1pf(__expf(-fabsf(x))) + fmaxf(x, 0.0f);
}

__global__ void __launch_bounds__(256, 8)
k_main(const float* __restrict__ pred, const float* __restrict__ targets,
       float* __restrict__ out) {
    const int tid  = threadIdx.x;
    const int blk  = blockIdx.x;
    const int lane = tid & 31;
    const int warp = tid >> 5;

    // ---- conf load issued first (overlaps target branch) ----
    const int ci = blk * 256 + tid;                 // < NCELL exactly
    const float cv = __ldg(&pred[(size_t)ci * DD + 4]);

    __shared__ float s_c[8], s_l[8], s_o[8], s_r[8];
    __shared__ int   s_n[8];
    __shared__ bool  isLast;

    // ---- target branch: blocks 0..399, 8 targets each (warp-per-target) ----
    if (blk < NTBLK) {
        const int tg   = blk * 8 + warp;            // global target id < NT
        const int b    = tg / TT;
        const int tIdx = tg % TT;

        // all lanes load this target's 5 fields (uniform address -> broadcast)
        const float* tp = targets + (size_t)tg * 5;
        const int   cid = (int)tp[0];
        const float cx = tp[1], cy = tp[2], w = tp[3], h = tp[4];
        const int gx = (int)floorf(cx * WW);
        const int gy = (int)floorf(cy * HH);
        const int cell = gy * WW + gx;
        const float tx = cx * WW - (float)gx;
        const float ty = cy * HH - (float)gy;

        // dedup: any earlier target j<tIdx in this batch with the same cell?
        bool hit = false;
        #pragma unroll
        for (int r = 0; r < 2; r++) {
            int j = lane + r * 32;
            if (j < tIdx) {
                const float* pj = targets + ((size_t)b * TT + j) * 5;
                int pgx = (int)floorf(pj[1] * WW);
                int pgy = (int)floorf(pj[2] * HH);
                if (pgy * WW + pgx == cell) hit = true;
            }
        }
        const bool uniq = (__ballot_sync(0xffffffffu, hit) == 0u);

        // warp-cooperative logsumexp over 80 classes
        const float* g = pred + ((size_t)b * HWC + cell) * DD;
        float v0 = __ldg(&g[5 + lane]);
        float v1 = __ldg(&g[5 + 32 + lane]);
        float v2 = (lane < 16) ? __ldg(&g[5 + 64 + lane]) : -1e30f;
        float m = fmaxf(fmaxf(v0, v1), v2);
        #pragma unroll
        for (int o = 16; o > 0; o >>= 1)
            m = fmaxf(m, __shfl_xor_sync(0xffffffffu, m, o));
        float s = __expf(v0 - m) + __expf(v1 - m) +
                  ((lane < 16) ? __expf(v2 - m) : 0.0f);
        #pragma unroll
        for (int o = 16; o > 0; o >>= 1)
            s += __shfl_xor_sync(0xffffffffu, s, o);

        if (lane == 0) {
            float clsv = -(__ldg(&g[5 + cid]) - m - logf(s));
            float sx = 1.0f / (1.0f + __expf(-__ldg(&g[0])));
            float sy = 1.0f / (1.0f + __expf(-__ldg(&g[1])));
            float tw = logf(w * WW + 1e-16f);
            float th = logf(h * HH + 1e-16f);
            float dx = sx - tx, dy = sy - ty;
            float dw = __ldg(&g[2]) - tw, dh = __ldg(&g[3]) - th;
            float coordv = 0.5f * (dx * dx + dy * dy) + 0.5f * (dw * dw + dh * dh);
            float objv = 0.f, corrv = 0.f;
            if (uniq) {
                float cl = __ldg(&g[4]);
                float bse = log1pf(__expf(-fabsf(cl)));
                objv  = bse + fmaxf(-cl, 0.0f);   // softplus(-cl)
                corrv = bse + fmaxf( cl, 0.0f);   // softplus(cl)
            }
            s_c[warp] = coordv; s_l[warp] = clsv;
            s_o[warp] = objv;   s_r[warp] = corrv;
            s_n[warp] = uniq ? 1 : 0;
        }
        __syncthreads();
        if (tid == 0) {
            float a = 0, bsum = 0, c = 0, d = 0; int n = 0;
            #pragma unroll
            for (int i = 0; i < 8; i++) {
                a += s_c[i]; bsum += s_l[i]; c += s_o[i]; d += s_r[i]; n += s_n[i];
            }
            g_coord_part[blk] = a; g_cls_part[blk] = bsum;
            g_obj_part[blk] = c;   g_corr_part[blk] = d;
            g_cnt_part[blk] = n;
        }
        __syncthreads();   // protect s_c reuse below
    }

    // ---- conf partial: block-reduce softplus (8 warps) ----
    {
        float s = softplus_pos(cv);
        #pragma unroll
        for (int o = 16; o > 0; o >>= 1)
            s += __shfl_xor_sync(0xffffffffu, s, o);
        if (lane == 0) s_c[warp] = s;
        __syncthreads();
        if (tid == 0) {
            float t = 0;
            #pragma unroll
            for (int i = 0; i < 8; i++) t += s_c[i];
            g_conf_part[blk] = t;
        }
    }

    // ---- last-block ticket ----
    __threadfence();
    if (tid == 0) {
        unsigned old = atomicAdd(&g_counter, 1);
        isLast = (old == (unsigned)(NCBLK - 1));
    }
    __syncthreads();
    if (!isLast) return;
    __threadfence();

    // ---- finalize in this 256-thread block: one-pass parallel reduce ----
    // Issue ALL partial loads up front (independent -> MLP).
    double vconf = 0.0;
    #pragma unroll
    for (int r = 0; r < NCBLK / 256; r++)          // 6 full rounds (1536)
        vconf += (double)g_conf_part[tid + r * 256];
    if (tid < NCBLK - (NCBLK / 256) * 256 + 0) {}  // (1600 = 6*256 + 64)
    if (tid < 64) vconf += (double)g_conf_part[1536 + tid];

    double vcoord = 0.0, vcls = 0.0, vobj = 0.0, vcorr = 0.0, vcnt = 0.0;
    #pragma unroll
    for (int r = 0; r < 2; r++) {                  // 400 = 2*200; use stride 256
        int i = tid + r * 256;
        if (i < NTBLK) {
            vcoord += (double)g_coord_part[i];
            vcls   += (double)g_cls_part[i];
            vobj   += (double)g_obj_part[i];
            vcorr  += (double)g_corr_part[i];
            vcnt   += (double)g_cnt_part[i];
        }
    }

    // six parallel warp reductions -> shared [6][8] -> single sync -> combine
    __shared__ double sred[6][8];
    #pragma unroll
    for (int o = 16; o > 0; o >>= 1) {
        vconf  += __shfl_xor_sync(0xffffffffu, vconf,  o);
        vcoord += __shfl_xor_sync(0xffffffffu, vcoord, o);
        vcls   += __shfl_xor_sync(0xffffffffu, vcls,   o);
        vobj   += __shfl_xor_sync(0xffffffffu, vobj,   o);
        vcorr  += __shfl_xor_sync(0xffffffffu, vcorr,  o);
        vcnt   += __shfl_xor_sync(0xffffffffu, vcnt,   o);
    }
    if (lane == 0) {
        sred[0][warp] = vconf;  sred[1][warp] = vcoord; sred[2][warp] = vcls;
        sred[3][warp] = vobj;   sred[4][warp] = vcorr;  sred[5][warp] = vcnt;
    }
    __syncthreads();

    if (tid == 0) {
        double alls = 0, coord = 0, cls = 0, objs = 0, corr = 0, cnt = 0;
        #pragma unroll
        for (int i = 0; i < 8; i++) {
            alls += sred[0][i]; coord += sred[1][i]; cls += sred[2][i];
            objs += sred[3][i]; corr  += sred[4][i]; cnt += sred[5][i];
        }
        int nobj = (int)(cnt + 0.5);
        double n_noobj = (double)(NCELL - nobj);
        double noobj_sum = alls - corr;
        double conf_obj = objs / (double)(nobj > 0 ? nobj : 1);
        double conf_noobj = noobj_sum / n_noobj;
        double num_obj = (double)NT;
        double total = LAMBDA_COORD * coord / num_obj
                     + conf_obj / num_obj
                     + LAMBDA_NOOBJ * conf_noobj / n_noobj
                     + cls / num_obj;
        out[0] = (float)total;
        g_counter = 0;   // reset for next graph replay
    }
}

extern "C" void kernel_launch(void* const* d_in, const int* in_sizes, int n_in,
                              void* d_out, int out_size) {
    const float* pred    = (const float*)d_in[0];
    const float* targets = (const float*)d_in[1];
    float* out = (float*)d_out;
    (void)in_sizes; (void)n_in; (void)out_size;

    k_main<<<NCBLK, 256>>>(pred, targets, out);
}

// round 8
// speedup vs baseline: 1.6807x; 1.0422x over previous
#include <cuda_runtime.h>
#include <math.h>

// Fixed shapes: (B,H,W,C,T) = (64,80,80,80,50)
#define BB    64
#define HH    80
#define WW    80
#define HWC   (HH*WW)          // 6400
#define CC    80
#define DD    (5+CC)           // 85
#define TT    50
#define NT    (BB*TT)          // 3200
#define NCELL (BB*HWC)         // 409600

#define NCBLK 800              // 800 x 256 x 2 = 409600
#define NTBLK 400              // blocks that also carry 8 targets each

#define LAMBDA_COORD 5.0
#define LAMBDA_NOOBJ 0.5

// Per-block partials: every slot written on every replay -> no init kernel.
__device__ float g_conf_part[NCBLK];
__device__ float g_coord_part[NTBLK];
__device__ float g_cls_part[NTBLK];
__device__ float g_obj_part[NTBLK];
__device__ float g_corr_part[NTBLK];
__device__ int   g_cnt_part[NTBLK];
__device__ unsigned int g_counter = 0;   // reset by finalizing block each replay

__device__ __forceinline__ float softplus_pos(float x) {
    return log1pf(__expf(-fabsf(x))) + fmaxf(x, 0.0f);
}

__global__ void __launch_bounds__(256, 8)
k_main(const float* __restrict__ pred, const float* __restrict__ targets,
       float* __restrict__ out) {
    const int tid  = threadIdx.x;
    const int blk  = blockIdx.x;
    const int lane = tid & 31;
    const int warp = tid >> 5;

    // ---- both conf loads issued first (independent -> MLP=2) ----
    const int i0 = blk * 512 + tid;                 // < NCELL
    const int i1 = i0 + 256;
    const float c0 = __ldg(&pred[(size_t)i0 * DD + 4]);
    const float c1 = __ldg(&pred[(size_t)i1 * DD + 4]);

    __shared__ float s_c[8], s_l[8], s_o[8], s_r[8];
    __shared__ int   s_n[8];
    __shared__ bool  isLast;

    // ---- target branch: blocks 0..399, 8 targets each (warp-per-target) ----
    if (blk < NTBLK) {
        const int tg   = blk * 8 + warp;            // global target id < NT
        const int b    = tg / TT;
        const int tIdx = tg % TT;

        // all lanes load this target's 5 fields (uniform address -> broadcast)
        const float* tp = targets + (size_t)tg * 5;
        const int   cid = (int)tp[0];
        const float cx = tp[1], cy = tp[2], w = tp[3], h = tp[4];
        const int gx = (int)floorf(cx * WW);
        const int gy = (int)floorf(cy * HH);
        const int cell = gy * WW + gx;
        const float tx = cx * WW - (float)gx;
        const float ty = cy * HH - (float)gy;

        // dedup: any earlier target j<tIdx in this batch with the same cell?
        bool hit = false;
        #pragma unroll
        for (int r = 0; r < 2; r++) {
            int j = lane + r * 32;
            if (j < tIdx) {
                const float* pj = targets + ((size_t)b * TT + j) * 5;
                int pgx = (int)floorf(pj[1] * WW);
                int pgy = (int)floorf(pj[2] * HH);
                if (pgy * WW + pgx == cell) hit = true;
            }
        }
        const bool uniq = (__ballot_sync(0xffffffffu, hit) == 0u);

        // warp-cooperative logsumexp over 80 classes
        const float* g = pred + ((size_t)b * HWC + cell) * DD;
        float v0 = __ldg(&g[5 + lane]);
        float v1 = __ldg(&g[5 + 32 + lane]);
        float v2 = (lane < 16) ? __ldg(&g[5 + 64 + lane]) : -1e30f;
        float m = fmaxf(fmaxf(v0, v1), v2);
        #pragma unroll
        for (int o = 16; o > 0; o >>= 1)
            m = fmaxf(m, __shfl_xor_sync(0xffffffffu, m, o));
        float s = __expf(v0 - m) + __expf(v1 - m) +
                  ((lane < 16) ? __expf(v2 - m) : 0.0f);
        #pragma unroll
        for (int o = 16; o > 0; o >>= 1)
            s += __shfl_xor_sync(0xffffffffu, s, o);

        if (lane == 0) {
            float clsv = -(__ldg(&g[5 + cid]) - m - logf(s));
            float sx = 1.0f / (1.0f + __expf(-__ldg(&g[0])));
            float sy = 1.0f / (1.0f + __expf(-__ldg(&g[1])));
            float tw = logf(w * WW + 1e-16f);
            float th = logf(h * HH + 1e-16f);
            float dx = sx - tx, dy = sy - ty;
            float dw = __ldg(&g[2]) - tw, dh = __ldg(&g[3]) - th;
            float coordv = 0.5f * (dx * dx + dy * dy) + 0.5f * (dw * dw + dh * dh);
            float objv = 0.f, corrv = 0.f;
            if (uniq) {
                float cl = __ldg(&g[4]);
                float bse = log1pf(__expf(-fabsf(cl)));
                objv  = bse + fmaxf(-cl, 0.0f);   // softplus(-cl)
                corrv = bse + fmaxf( cl, 0.0f);   // softplus(cl)
            }
            s_c[warp] = coordv; s_l[warp] = clsv;
            s_o[warp] = objv;   s_r[warp] = corrv;
            s_n[warp] = uniq ? 1 : 0;
        }
        __syncthreads();
        if (tid == 0) {
            float a = 0, bsum = 0, c = 0, d = 0; int n = 0;
            #pragma unroll
            for (int i = 0; i < 8; i++) {
                a += s_c[i]; bsum += s_l[i]; c += s_o[i]; d += s_r[i]; n += s_n[i];
            }
            g_coord_part[blk] = a; g_cls_part[blk] = bsum;
            g_obj_part[blk] = c;   g_corr_part[blk] = d;
            g_cnt_part[blk] = n;
        }
        __syncthreads();   // protect s_c reuse below
    }

    // ---- conf partial: block-reduce softplus of both cells (8 warps) ----
    {
        float s = softplus_pos(c0) + softplus_pos(c1);
        #pragma unroll
        for (int o = 16; o > 0; o >>= 1)
            s += __shfl_xor_sync(0xffffffffu, s, o);
        if (lane == 0) s_c[warp] = s;
        __syncthreads();
        if (tid == 0) {
            float t = 0;
            #pragma unroll
            for (int i = 0; i < 8; i++) t += s_c[i];
            g_conf_part[blk] = t;
        }
    }

    // ---- last-block ticket ----
    __threadfence();
    if (tid == 0) {
        unsigned old = atomicAdd(&g_counter, 1);
        isLast = (old == (unsigned)(NCBLK - 1));
    }
    __syncthreads();
    if (!isLast) return;
    __threadfence();

    // ---- finalize in this 256-thread block: one-pass parallel reduce ----
    double vconf = 0.0;
    #pragma unroll
    for (int r = 0; r < NCBLK / 256; r++)          // 3 full rounds (768)
        vconf += (double)g_conf_part[tid + r * 256];
    if (tid < NCBLK - (NCBLK / 256) * 256)         // remainder 32
        vconf += (double)g_conf_part[(NCBLK / 256) * 256 + tid];

    double vcoord = 0.0, vcls = 0.0, vobj = 0.0, vcorr = 0.0, vcnt = 0.0;
    #pragma unroll
    for (int r = 0; r < 2; r++) {                  // 400 partials
        int i = tid + r * 256;
        if (i < NTBLK) {
            vcoord += (double)g_coord_part[i];
            vcls   += (double)g_cls_part[i];
            vobj   += (double)g_obj_part[i];
            vcorr  += (double)g_corr_part[i];
            vcnt   += (double)g_cnt_part[i];
        }
    }

    // six parallel warp reductions -> shared [6][8] -> single sync -> combine
    __shared__ double sred[6][8];
    #pragma unroll
    for (int o = 16; o > 0; o >>= 1) {
        vconf  += __shfl_xor_sync(0xffffffffu, vconf,  o);
        vcoord += __shfl_xor_sync(0xffffffffu, vcoord, o);
        vcls   += __shfl_xor_sync(0xffffffffu, vcls,   o);
        vobj   += __shfl_xor_sync(0xffffffffu, vobj,   o);
        vcorr  += __shfl_xor_sync(0xffffffffu, vcorr,  o);
        vcnt   += __shfl_xor_sync(0xffffffffu, vcnt,   o);
    }
    if (lane == 0) {
        sred[0][warp] = vconf;  sred[1][warp] = vcoord; sred[2][warp] = vcls;
        sred[3][warp] = vobj;   sred[4][warp] = vcorr;  sred[5][warp] = vcnt;
    }
    __syncthreads();

    if (tid == 0) {
        double alls = 0, coord = 0, cls = 0, objs = 0, corr = 0, cnt = 0;
        #pragma unroll
        for (int i = 0; i < 8; i++) {
            alls += sred[0][i]; coord += sred[1][i]; cls += sred[2][i];
            objs += sred[3][i]; corr  += sred[4][i]; cnt += sred[5][i];
        }
        int nobj = (int)(cnt + 0.5);
        double n_noobj = (double)(NCELL - nobj);
        double noobj_sum = alls - corr;
        double conf_obj = objs / (double)(nobj > 0 ? nobj : 1);
        double conf_noobj = noobj_sum / n_noobj;
        double num_obj = (double)NT;
        double total = LAMBDA_COORD * coord / num_obj
                     + conf_obj / num_obj
                     + LAMBDA_NOOBJ * conf_noobj / n_noobj
                     + cls / num_obj;
        out[0] = (float)total;
        g_counter = 0;   // reset for next graph replay
    }
}

extern "C" void kernel_launch(void* const* d_in, const int* in_sizes, int n_in,
                              void* d_out, int out_size) {
    const float* pred    = (const float*)d_in[0];
    const float* targets = (const float*)d_in[1];
    float* out = (float*)d_out;
    (void)in_sizes; (void)n_in; (void)out_size;

    k_main<<<NCBLK, 256>>>(pred, targets, out);
}